// round 1
// baseline (speedup 1.0000x reference)
#include <cuda_runtime.h>
#include <cstdint>

// Problem constants
// x: (4, 512, 256, 64) f32, s: (4,256), W: (512,768), b: (512)
// out: (4, 512, 256, 64) f32
#define DEV_INLINE __device__ __forceinline__

constexpr int Bn = 4, T = 256, H = 64, C1 = 512, AUX = 256, OUTC = 512;
constexpr int KTOT = C1 + AUX; // 768

// Scratch (static device globals: allowed; no dynamic allocation)
__device__ float g_sbias[Bn * OUTC];     // per-batch bias incl. s @ W2^T
__device__ float g_wc[OUTC * C1];        // W1 pre-converted to tf32 (rna)

// ---------------- prologue kernels ----------------

__global__ void sbias_kernel(const float* __restrict__ s,
                             const float* __restrict__ W,
                             const float* __restrict__ bias) {
    int idx = blockIdx.x * blockDim.x + threadIdx.x;   // 2048 threads
    int b = idx >> 9, o = idx & 511;
    float acc = bias[o];
    const float* wrow = W + o * KTOT + C1;
    const float* srow = s + b * AUX;
#pragma unroll 8
    for (int j = 0; j < AUX; ++j) acc += srow[j] * wrow[j];
    g_sbias[idx] = acc;
}

__global__ void wconv_kernel(const float* __restrict__ W) {
    int idx = blockIdx.x * blockDim.x + threadIdx.x;   // 262144 threads
    int o = idx >> 9, c = idx & 511;
    float v = W[o * KTOT + c];
    uint32_t u;
    asm("cvt.rna.tf32.f32 %0, %1;" : "=r"(u) : "f"(v));
    g_wc[idx] = __uint_as_float(u);
}

// ---------------- helpers ----------------

DEV_INLINE void cpa16(uint32_t dst, const float* src) {
    asm volatile("cp.async.cg.shared.global [%0], [%1], 16;\n" :: "r"(dst), "l"(src));
}
DEV_INLINE void cpa_commit() { asm volatile("cp.async.commit_group;\n"); }
template <int N> DEV_INLINE void cpa_wait() {
    asm volatile("cp.async.wait_group %0;\n" :: "n"(N));
}

DEV_INLINE void mma_tf32(float* d, const uint32_t* a, const uint32_t* bb) {
    asm volatile(
        "mma.sync.aligned.m16n8k8.row.col.f32.tf32.tf32.f32 "
        "{%0,%1,%2,%3}, {%4,%5,%6,%7}, {%8,%9}, {%0,%1,%2,%3};\n"
        : "+f"(d[0]), "+f"(d[1]), "+f"(d[2]), "+f"(d[3])
        : "r"(a[0]), "r"(a[1]), "r"(a[2]), "r"(a[3]), "r"(bb[0]), "r"(bb[1]));
}

DEV_INLINE uint32_t f2tf32(float v) {
    uint32_t u;
    asm("cvt.rna.tf32.f32 %0, %1;" : "=r"(u) : "f"(v));
    return u;
}

// ---------------- main fused kernel ----------------
// Grid: 1024 CTAs, one (b,t) each. CTA tile: 64(h=M) x 512(o=N), K=512.
// 512 threads, 16 warps: wm in {0,1} (32 rows), wn in 0..7 (64 cols).
// Per warp: 2 m-tiles(16) x 8 n-tiles(8); per thread 64 fp32 accums.
// Smem (floats), all offsets below:
constexpr int SA_STRIDE = 72;   // 64 + 8 -> banks (8k+m)%32 distinct
constexpr int SB_STRIDE = 20;   // 16 + 4 -> banks (20n+k)%32 distinct
constexpr int SA_OFF = 0;                       // 2*16*72   = 2304
constexpr int SB_OFF = 2304;                    // 2*512*20  = 20480
constexpr int RS_OFF = SB_OFF + 20480;          // 64*8 = 512
constexpr int RQ_OFF = RS_OFF + 512;            // 512
constexpr int MU_OFF = RQ_OFF + 512;            // 64
constexpr int RSTD_OFF = MU_OFF + 64;           // 64
constexpr int LW_OFF = RSTD_OFF + 64;           // 512
constexpr int LB_OFF = LW_OFF + 512;            // 512
constexpr int SBIA_OFF = LB_OFF + 512;          // 512
constexpr int SMEM_FLOATS = SBIA_OFF + 512;     // 25472 floats
constexpr int SMEM_BYTES = SMEM_FLOATS * 4;     // 101888 B

__global__ __launch_bounds__(512, 1)
void fused_kernel(const float* __restrict__ x,
                  const float* __restrict__ prelu_a,
                  const float* __restrict__ lnw,
                  const float* __restrict__ lnb,
                  float* __restrict__ out) {
    extern __shared__ float sm[];
    const int tid = threadIdx.x;
    const int bt = blockIdx.x;
    const int b = bt >> 8;
    const int t = bt & 255;

    // epilogue constants to smem (consumed after many __syncthreads)
    sm[LW_OFF + tid] = lnw[tid];
    sm[LB_OFF + tid] = lnb[tid];
    sm[SBIA_OFF + tid] = g_sbias[b * 512 + tid];

    const uint32_t smb = (uint32_t)__cvta_generic_to_shared(sm);

    const int lane = tid & 31, w = tid >> 5;
    const int wm = w >> 3;        // 0..1
    const int wn = w & 7;         // 0..7
    const int qid = lane >> 2;    // 0..7
    const int tig = lane & 3;     // 0..3

    auto load_tiles = [&](int kt, int buf) {
        const int k0 = kt * 16;
        // A tile: 16 c-rows x 64 h floats = 256 x 16B chunks
        if (tid < 256) {
            int c = tid >> 4, j = tid & 15;
            const float* src =
                x + (((size_t)(b * 512 + k0 + c) * 256 + t) * 64) + j * 4;
            cpa16(smb + 4u * (SA_OFF + buf * (16 * SA_STRIDE) + c * SA_STRIDE + j * 4), src);
        }
        // B tile: 512 o-rows x 16 k floats = 2048 x 16B chunks, 4/thread
#pragma unroll
        for (int p = 0; p < 4; ++p) {
            int o = p * 128 + (tid >> 2), j = tid & 3;
            const float* src = g_wc + o * 512 + k0 + j * 4;
            cpa16(smb + 4u * (SB_OFF + buf * (512 * SB_STRIDE) + o * SB_STRIDE + j * 4), src);
        }
        cpa_commit();
    };

    float acc[2][8][4];
#pragma unroll
    for (int mt = 0; mt < 2; ++mt)
#pragma unroll
        for (int nt = 0; nt < 8; ++nt)
#pragma unroll
            for (int r = 0; r < 4; ++r) acc[mt][nt][r] = 0.f;

    load_tiles(0, 0);

    for (int kt = 0; kt < 32; ++kt) {
        const int buf = kt & 1;
        if (kt + 1 < 32) {
            load_tiles(kt + 1, buf ^ 1);
            cpa_wait<1>();
        } else {
            cpa_wait<0>();
        }
        __syncthreads();

        const float* A = sm + SA_OFF + buf * (16 * SA_STRIDE);
        const float* Bt = sm + SB_OFF + buf * (512 * SB_STRIDE);

#pragma unroll
        for (int ks = 0; ks < 2; ++ks) {
            const int kb = ks * 8;
            uint32_t a[2][4];
#pragma unroll
            for (int mt = 0; mt < 2; ++mt) {
                const int m0 = wm * 32 + mt * 16 + qid;
                a[mt][0] = f2tf32(A[(kb + tig) * SA_STRIDE + m0]);
                a[mt][1] = f2tf32(A[(kb + tig) * SA_STRIDE + m0 + 8]);
                a[mt][2] = f2tf32(A[(kb + tig + 4) * SA_STRIDE + m0]);
                a[mt][3] = f2tf32(A[(kb + tig + 4) * SA_STRIDE + m0 + 8]);
            }
#pragma unroll
            for (int nt = 0; nt < 8; ++nt) {
                const int n = wn * 64 + nt * 8 + qid;
                uint32_t bb[2];
                bb[0] = __float_as_uint(Bt[n * SB_STRIDE + kb + tig]);
                bb[1] = __float_as_uint(Bt[n * SB_STRIDE + kb + tig + 4]);
                mma_tf32(acc[0][nt], a[0], bb);
                mma_tf32(acc[1][nt], a[1], bb);
            }
        }
        __syncthreads();
    }

    // ---------------- epilogue: +sbias, PReLU, LayerNorm, residual, store ----------------
    const float pa = prelu_a[0];

    float srow[4] = {0.f, 0.f, 0.f, 0.f};
    float qrow[4] = {0.f, 0.f, 0.f, 0.f};
#pragma unroll
    for (int mt = 0; mt < 2; ++mt)
#pragma unroll
        for (int nt = 0; nt < 8; ++nt)
#pragma unroll
            for (int r = 0; r < 4; ++r) {
                const int half = r >> 1;
                const int n = wn * 64 + nt * 8 + tig * 2 + (r & 1);
                float v = acc[mt][nt][r] + sm[SBIA_OFF + n];
                v = (v >= 0.f) ? v : pa * v;
                acc[mt][nt][r] = v;
                srow[mt * 2 + half] += v;
                qrow[mt * 2 + half] += v * v;
            }
    // reduce across the 4 lanes of each quad (same row, different cols)
#pragma unroll
    for (int off = 1; off <= 2; off <<= 1)
#pragma unroll
        for (int i = 0; i < 4; ++i) {
            srow[i] += __shfl_xor_sync(0xffffffffu, srow[i], off);
            qrow[i] += __shfl_xor_sync(0xffffffffu, qrow[i], off);
        }
    if (tig == 0) {
#pragma unroll
        for (int i = 0; i < 4; ++i) {
            const int rrow = wm * 32 + (i >> 1) * 16 + (i & 1) * 8 + qid;
            sm[RS_OFF + rrow * 8 + wn] = srow[i];
            sm[RQ_OFF + rrow * 8 + wn] = qrow[i];
        }
    }
    __syncthreads();
    if (tid < 64) {
        float s = 0.f, q = 0.f;
#pragma unroll
        for (int j = 0; j < 8; ++j) {
            s += sm[RS_OFF + tid * 8 + j];
            q += sm[RQ_OFF + tid * 8 + j];
        }
        const float mu = s * (1.f / 512.f);
        float var = q * (1.f / 512.f) - mu * mu;
        var = fmaxf(var, 0.f);
        sm[MU_OFF + tid] = mu;
        sm[RSTD_OFF + tid] = rsqrtf(var + 1e-8f);
    }
    __syncthreads();

    float mu4[4], rs4[4];
#pragma unroll
    for (int i = 0; i < 4; ++i) {
        const int rrow = wm * 32 + (i >> 1) * 16 + (i & 1) * 8 + qid;
        mu4[i] = sm[MU_OFF + rrow];
        rs4[i] = sm[RSTD_OFF + rrow];
    }

    const size_t base = ((size_t)b * 512 * 256 + t) * 64;  // + n*16384 + h
#pragma unroll
    for (int mt = 0; mt < 2; ++mt)
#pragma unroll
        for (int nt = 0; nt < 8; ++nt)
#pragma unroll
            for (int r = 0; r < 4; ++r) {
                const int i = mt * 2 + (r >> 1);
                const int rrow = wm * 32 + mt * 16 + (r >> 1) * 8 + qid;
                const int n = wn * 64 + nt * 8 + tig * 2 + (r & 1);
                const size_t gi = base + (size_t)n * 16384 + rrow;
                const float yv =
                    (acc[mt][nt][r] - mu4[i]) * rs4[i] * sm[LW_OFF + n] +
                    sm[LB_OFF + n] + __ldg(x + gi);
                out[gi] = yv;
            }
}

// ---------------- launch ----------------

extern "C" void kernel_launch(void* const* d_in, const int* in_sizes, int n_in,
                              void* d_out, int out_size) {
    (void)in_sizes; (void)n_in; (void)out_size;
    const float* x      = (const float*)d_in[0];
    const float* s      = (const float*)d_in[1];
    // d_in[2..4] = prelu1_a, ln1_w, ln1_b : dead code in the reference
    const float* W      = (const float*)d_in[5];
    const float* bias   = (const float*)d_in[6];
    const float* prelu2 = (const float*)d_in[7];
    const float* ln2w   = (const float*)d_in[8];
    const float* ln2b   = (const float*)d_in[9];
    float* out = (float*)d_out;

    cudaFuncSetAttribute(fused_kernel,
                         cudaFuncAttributeMaxDynamicSharedMemorySize, SMEM_BYTES);

    sbias_kernel<<<8, 256>>>(s, W, bias);
    wconv_kernel<<<1024, 256>>>(W);
    fused_kernel<<<Bn * T, 512, SMEM_BYTES>>>(x, prelu2, ln2w, ln2b, out);
}

// round 3
// speedup vs baseline: 1.5575x; 1.5575x over previous
#include <cuda_runtime.h>
#include <cstdint>

#define DEV_INLINE __device__ __forceinline__

constexpr int KTOT = 768;
constexpr int NSTAGES = 16, KSTAGE = 32;     // K = 512
constexpr int SB_STRIDE = 36;                // 32 k floats + 4 pad  (bank-conflict-free)
constexpr int SA_STRIDE = 72;                // 64 m floats + 8 pad  (bank-conflict-free)
constexpr int B_STAGE_BYTES = 512 * SB_STRIDE * 4;   // 73728
constexpr int A_STAGE_BYTES = KSTAGE * SA_STRIDE * 4; // 9216

// static device scratch
__device__ float g_sbias[4 * 512];
__device__ __align__(128) float g_wst[NSTAGES * 512 * SB_STRIDE]; // tf32 W, padded stage image

// ---------------- PTX helpers ----------------

DEV_INLINE uint32_t smem_u32(const void* p) {
    uint32_t a;
    asm("{ .reg .u64 t; cvta.to.shared.u64 t, %1; cvt.u32.u64 %0, t; }" : "=r"(a) : "l"(p));
    return a;
}
DEV_INLINE uint32_t f2tf32(float v) {
    uint32_t u; asm("cvt.rna.tf32.f32 %0, %1;" : "=r"(u) : "f"(v)); return u;
}
DEV_INLINE void mbar_init(uint32_t a, uint32_t cnt) {
    asm volatile("mbarrier.init.shared.b64 [%0], %1;" :: "r"(a), "r"(cnt) : "memory");
}
DEV_INLINE void mbar_expect_tx(uint32_t a, uint32_t bytes) {
    asm volatile("mbarrier.arrive.expect_tx.shared.b64 _, [%0], %1;" :: "r"(a), "r"(bytes) : "memory");
}
DEV_INLINE void mbar_wait(uint32_t a, uint32_t parity) {
    asm volatile(
        "{ .reg .pred P;\n"
        "W_%=:\n"
        " mbarrier.try_wait.parity.acquire.cta.shared::cta.b64 P, [%0], %1, 0x989680;\n"
        " @P bra.uni D_%=;\n"
        " bra.uni W_%=;\n"
        "D_%=:\n}"
        :: "r"(a), "r"(parity) : "memory");
}
DEV_INLINE void bulk_g2s(uint32_t dst, const void* src, uint32_t bytes, uint32_t mbar) {
    asm volatile(
        "cp.async.bulk.shared::cluster.global.mbarrier::complete_tx::bytes [%0], [%1], %2, [%3];"
        :: "r"(dst), "l"(src), "r"(bytes), "r"(mbar) : "memory");
}
DEV_INLINE void cpa16(uint32_t dst, const float* src) {
    asm volatile("cp.async.cg.shared.global [%0], [%1], 16;\n" :: "r"(dst), "l"(src));
}
DEV_INLINE void cpa_commit() { asm volatile("cp.async.commit_group;\n"); }
template <int N> DEV_INLINE void cpa_wait() {
    asm volatile("cp.async.wait_group %0;\n" :: "n"(N));
}
DEV_INLINE void mma_tf32(float* d, const uint32_t* a, const uint32_t* bb) {
    asm volatile(
        "mma.sync.aligned.m16n8k8.row.col.f32.tf32.tf32.f32 "
        "{%0,%1,%2,%3}, {%4,%5,%6,%7}, {%8,%9}, {%0,%1,%2,%3};\n"
        : "+f"(d[0]), "+f"(d[1]), "+f"(d[2]), "+f"(d[3])
        : "r"(a[0]), "r"(a[1]), "r"(a[2]), "r"(a[3]), "r"(bb[0]), "r"(bb[1]));
}

// ---------------- prologue kernels ----------------

__global__ void sbias_kernel(const float* __restrict__ s,
                             const float* __restrict__ W,
                             const float* __restrict__ bias) {
    int gw = (blockIdx.x * blockDim.x + threadIdx.x) >> 5;   // 2048 warps: (b,o)
    int lane = threadIdx.x & 31;
    int b = gw >> 9, o = gw & 511;
    const float* wrow = W + o * KTOT + 512;
    const float* srow = s + b * 256;
    float acc = 0.f;
#pragma unroll
    for (int j = 0; j < 8; ++j) acc += srow[lane + 32 * j] * wrow[lane + 32 * j];
#pragma unroll
    for (int off = 16; off; off >>= 1) acc += __shfl_xor_sync(0xffffffffu, acc, off);
    if (lane == 0) g_sbias[b * 512 + o] = acc + bias[o];
}

// W -> tf32(rna), written in the exact padded per-stage smem image
__global__ void wstage_kernel(const float* __restrict__ W) {
    int idx = blockIdx.x * blockDim.x + threadIdx.x;   // 16*512*36 = 294912
    int j = idx % SB_STRIDE;
    int rest = idx / SB_STRIDE;
    int o = rest & 511, stage = rest >> 9;
    float v = 0.f;
    if (j < KSTAGE) v = __uint_as_float(f2tf32(W[o * KTOT + stage * KSTAGE + j]));
    g_wst[idx] = v;
}

// ---------------- fused kernel ----------------
// Grid 1024: CTA = (b,t). Tile 64(m=h) x 512(n=o), K=512 in 16 stages of 32.
// 512 threads = 16 warps (2m x 8n), warp tile 32x64, per-thread 64 fp32 acc.

// smem byte offsets
constexpr int SM_MBAR = 0;                 // 2 mbarriers @ 0, 8
constexpr int F_RS   = 16;                 // float offsets
constexpr int F_RQ   = F_RS + 512;
constexpr int F_MU   = F_RQ + 512;
constexpr int F_RSTD = F_MU + 64;
constexpr int F_LW   = F_RSTD + 64;
constexpr int F_LB   = F_LW + 512;
constexpr int F_SBIA = F_LB + 512;         // ends 2704 floats = 10816 B
constexpr int SM_A   = 12288;              // 2 x 9216
constexpr int SM_B   = SM_A + 2 * A_STAGE_BYTES;   // 30720, 2 x 73728
constexpr int SMEM_BYTES = SM_B + 2 * B_STAGE_BYTES;  // 178176

__global__ __launch_bounds__(512, 1)
void fused_kernel(const float* __restrict__ x,
                  const float* __restrict__ prelu_a,
                  const float* __restrict__ lnw,
                  const float* __restrict__ lnb,
                  float* __restrict__ out) {
    extern __shared__ float smf[];
    const uint32_t smb = smem_u32(smf);
    const int tid = threadIdx.x;
    const int b = blockIdx.x >> 8;
    const int t = blockIdx.x & 255;

    // epilogue constants
    smf[F_LW + tid]   = lnw[tid];
    smf[F_LB + tid]   = lnb[tid];
    smf[F_SBIA + tid] = g_sbias[b * 512 + tid];

    if (tid == 0) { mbar_init(smb + SM_MBAR, 1); mbar_init(smb + SM_MBAR + 8, 1); }
    __syncthreads();

    const int lane = tid & 31, w = tid >> 5;
    const int wm = w >> 3, wn = w & 7;
    const int qid = lane >> 2, tig = lane & 3;
    const int ac = tid >> 4;   // k row 0..31
    const int aj = tid & 15;   // 16B chunk 0..15

    // stage loader: B via one bulk op (tid 0), A via one cp.async per thread
    auto load_stage = [&](int s, int buf) {
        if (tid == 0) {
            uint32_t mb = smb + SM_MBAR + 8 * buf;
            mbar_expect_tx(mb, B_STAGE_BYTES);
            bulk_g2s(smb + SM_B + buf * B_STAGE_BYTES,
                     g_wst + s * 512 * SB_STRIDE, B_STAGE_BYTES, mb);
        }
        const float* srcA = x + ((size_t)(b * 512 + s * KSTAGE + ac) * 256 + t) * 64 + aj * 4;
        cpa16(smb + SM_A + buf * A_STAGE_BYTES + ac * (SA_STRIDE * 4) + aj * 16, srcA);
        cpa_commit();
    };

    float acc[2][8][4];
#pragma unroll
    for (int mt = 0; mt < 2; ++mt)
#pragma unroll
        for (int nt = 0; nt < 8; ++nt)
#pragma unroll
            for (int r = 0; r < 4; ++r) acc[mt][nt][r] = 0.f;

    load_stage(0, 0);
    load_stage(1, 1);
    int ph[2] = {0, 0};

    for (int s = 0; s < NSTAGES; ++s) {
        const int buf = s & 1;
        mbar_wait(smb + SM_MBAR + 8 * buf, ph[buf]);
        ph[buf] ^= 1;
        if (s == NSTAGES - 1) cpa_wait<0>(); else cpa_wait<1>();
        __syncthreads();   // align consumers after waits (and before later producer reuse)

        const float* A  = smf + (SM_A >> 2) + buf * (A_STAGE_BYTES >> 2);
        const float* Bt = smf + (SM_B >> 2) + buf * (B_STAGE_BYTES >> 2);

#pragma unroll
        for (int ks = 0; ks < 4; ++ks) {
            const int kb = ks * 8;
            uint32_t a[2][4];
#pragma unroll
            for (int mt = 0; mt < 2; ++mt) {
                const int m0 = wm * 32 + mt * 16 + qid;
                a[mt][0] = f2tf32(A[(kb + tig) * SA_STRIDE + m0]);
                a[mt][1] = f2tf32(A[(kb + tig) * SA_STRIDE + m0 + 8]);
                a[mt][2] = f2tf32(A[(kb + tig + 4) * SA_STRIDE + m0]);
                a[mt][3] = f2tf32(A[(kb + tig + 4) * SA_STRIDE + m0 + 8]);
            }
#pragma unroll
            for (int nt = 0; nt < 8; ++nt) {
                const int n = wn * 64 + nt * 8 + qid;
                uint32_t bb[2];
                bb[0] = __float_as_uint(Bt[n * SB_STRIDE + kb + tig]);
                bb[1] = __float_as_uint(Bt[n * SB_STRIDE + kb + tig + 4]);
                mma_tf32(acc[0][nt], a[0], bb);
                mma_tf32(acc[1][nt], a[1], bb);
            }
        }
        __syncthreads();   // all warps done reading buf
        if (s + 2 < NSTAGES) load_stage(s + 2, buf);
    }

    // ---------------- epilogue: +sbias, PReLU, LayerNorm, residual ----------------
    const float pa = prelu_a[0];

    float srow[4] = {0.f, 0.f, 0.f, 0.f};
    float qrow[4] = {0.f, 0.f, 0.f, 0.f};
#pragma unroll
    for (int mt = 0; mt < 2; ++mt)
#pragma unroll
        for (int nt = 0; nt < 8; ++nt)
#pragma unroll
            for (int r = 0; r < 4; ++r) {
                const int half = r >> 1;
                const int n = wn * 64 + nt * 8 + tig * 2 + (r & 1);
                float v = acc[mt][nt][r] + smf[F_SBIA + n];
                v = (v >= 0.f) ? v : pa * v;
                acc[mt][nt][r] = v;
                srow[mt * 2 + half] += v;
                qrow[mt * 2 + half] += v * v;
            }
#pragma unroll
    for (int off = 1; off <= 2; off <<= 1)
#pragma unroll
        for (int i = 0; i < 4; ++i) {
            srow[i] += __shfl_xor_sync(0xffffffffu, srow[i], off);
            qrow[i] += __shfl_xor_sync(0xffffffffu, qrow[i], off);
        }
    if (tig == 0) {
#pragma unroll
        for (int i = 0; i < 4; ++i) {
            const int rrow = wm * 32 + (i >> 1) * 16 + (i & 1) * 8 + qid;
            smf[F_RS + rrow * 8 + wn] = srow[i];
            smf[F_RQ + rrow * 8 + wn] = qrow[i];
        }
    }
    __syncthreads();
    if (tid < 64) {
        float s8 = 0.f, q8 = 0.f;
#pragma unroll
        for (int j = 0; j < 8; ++j) {
            s8 += smf[F_RS + tid * 8 + j];
            q8 += smf[F_RQ + tid * 8 + j];
        }
        const float mu = s8 * (1.f / 512.f);
        float var = q8 * (1.f / 512.f) - mu * mu;
        var = fmaxf(var, 0.f);
        smf[F_MU + tid] = mu;
        smf[F_RSTD + tid] = rsqrtf(var + 1e-8f);
    }
    __syncthreads();

    float mu4[4], rs4[4];
#pragma unroll
    for (int i = 0; i < 4; ++i) {
        const int rrow = wm * 32 + (i >> 1) * 16 + (i & 1) * 8 + qid;
        mu4[i] = smf[F_MU + rrow];
        rs4[i] = smf[F_RSTD + rrow];
    }

    const size_t base = ((size_t)b * 512 * 256 + t) * 64;
#pragma unroll
    for (int mt = 0; mt < 2; ++mt)
#pragma unroll
        for (int nt = 0; nt < 8; ++nt)
#pragma unroll
            for (int r = 0; r < 4; ++r) {
                const int i = mt * 2 + (r >> 1);
                const int rrow = wm * 32 + mt * 16 + (r >> 1) * 8 + qid;
                const int n = wn * 64 + nt * 8 + tig * 2 + (r & 1);
                const size_t gi = base + (size_t)n * 16384 + rrow;
                out[gi] = (acc[mt][nt][r] - mu4[i]) * rs4[i] * smf[F_LW + n] +
                          smf[F_LB + n] + __ldg(x + gi);
            }
}

// ---------------- launch ----------------

extern "C" void kernel_launch(void* const* d_in, const int* in_sizes, int n_in,
                              void* d_out, int out_size) {
    (void)in_sizes; (void)n_in; (void)out_size;
    const float* x      = (const float*)d_in[0];
    const float* s      = (const float*)d_in[1];
    // d_in[2..4]: prelu1_a, ln1_w, ln1_b — dead code in the reference
    const float* W      = (const float*)d_in[5];
    const float* bias   = (const float*)d_in[6];
    const float* prelu2 = (const float*)d_in[7];
    const float* ln2w   = (const float*)d_in[8];
    const float* ln2b   = (const float*)d_in[9];
    float* out = (float*)d_out;

    cudaFuncSetAttribute(fused_kernel,
                         cudaFuncAttributeMaxDynamicSharedMemorySize, SMEM_BYTES);

    sbias_kernel<<<256, 256>>>(s, W, bias);
    wstage_kernel<<<1152, 256>>>(W);
    fused_kernel<<<1024, 512, SMEM_BYTES>>>(x, prelu2, ln2w, ln2b, out);
}

// round 4
// speedup vs baseline: 2.2833x; 1.4660x over previous
#include <cuda_runtime.h>
#include <cuda_fp16.h>
#include <cstdint>

#define DEV_INLINE __device__ __forceinline__

constexpr int KTOT = 768;
constexpr int NSTAGES = 8, KSTAGE = 64;          // K = 512
constexpr int SBW = 36;                           // u32 words per B row (32 kt + 4 pad)
constexpr int SAW = 68;                           // u32 words per A k-row (64 m + 4 pad)
constexpr int B_STAGE_BYTES = 512 * SBW * 4;      // 73728
constexpr int A_STAGE_BYTES = 32 * SAW * 4;       // 8704

// static device scratch
__device__ float g_sbias[4 * 512];
__device__ __align__(128) uint32_t g_wst[NSTAGES * 512 * SBW];  // fp16-packed, padded W stages

// ---------------- PTX helpers ----------------

DEV_INLINE uint32_t smem_u32(const void* p) {
    uint32_t a;
    asm("{ .reg .u64 t; cvta.to.shared.u64 t, %1; cvt.u32.u64 %0, t; }" : "=r"(a) : "l"(p));
    return a;
}
DEV_INLINE void mbar_init(uint32_t a, uint32_t cnt) {
    asm volatile("mbarrier.init.shared.b64 [%0], %1;" :: "r"(a), "r"(cnt) : "memory");
}
DEV_INLINE void mbar_expect_tx(uint32_t a, uint32_t bytes) {
    asm volatile("mbarrier.arrive.expect_tx.shared.b64 _, [%0], %1;" :: "r"(a), "r"(bytes) : "memory");
}
DEV_INLINE void mbar_wait(uint32_t a, uint32_t parity) {
    asm volatile(
        "{ .reg .pred P;\n"
        "W_%=:\n"
        " mbarrier.try_wait.parity.acquire.cta.shared::cta.b64 P, [%0], %1, 0x989680;\n"
        " @P bra.uni D_%=;\n"
        " bra.uni W_%=;\n"
        "D_%=:\n}"
        :: "r"(a), "r"(parity) : "memory");
}
DEV_INLINE void bulk_g2s(uint32_t dst, const void* src, uint32_t bytes, uint32_t mbar) {
    asm volatile(
        "cp.async.bulk.shared::cluster.global.mbarrier::complete_tx::bytes [%0], [%1], %2, [%3];"
        :: "r"(dst), "l"(src), "r"(bytes), "r"(mbar) : "memory");
}
DEV_INLINE void mma_f16(float* d, const uint32_t* a, const uint32_t* b) {
    asm volatile(
        "mma.sync.aligned.m16n8k16.row.col.f32.f16.f16.f32 "
        "{%0,%1,%2,%3}, {%4,%5,%6,%7}, {%8,%9}, {%0,%1,%2,%3};\n"
        : "+f"(d[0]), "+f"(d[1]), "+f"(d[2]), "+f"(d[3])
        : "r"(a[0]), "r"(a[1]), "r"(a[2]), "r"(a[3]), "r"(b[0]), "r"(b[1]));
}
DEV_INLINE uint32_t packh2(float lo, float hi) {
    __half2 h = __floats2half2_rn(lo, hi);   // .x = lo (low 16 bits)
    return *reinterpret_cast<uint32_t*>(&h);
}

// ---------------- prologue kernels ----------------

__global__ void sbias_kernel(const float* __restrict__ s,
                             const float* __restrict__ W,
                             const float* __restrict__ bias) {
    int gw = (blockIdx.x * blockDim.x + threadIdx.x) >> 5;   // 2048 warps: (b,o)
    int lane = threadIdx.x & 31;
    int b = gw >> 9, o = gw & 511;
    const float* wrow = W + o * KTOT + 512;
    const float* srow = s + b * 256;
    float acc = 0.f;
#pragma unroll
    for (int j = 0; j < 8; ++j) acc += srow[lane + 32 * j] * wrow[lane + 32 * j];
#pragma unroll
    for (int off = 16; off; off >>= 1) acc += __shfl_xor_sync(0xffffffffu, acc, off);
    if (lane == 0) g_sbias[b * 512 + o] = acc + bias[o];
}

// W -> fp16 pairs, exact padded per-stage smem image: word[s][n][kt] = (W[n][64s+2kt], W[n][64s+2kt+1])
__global__ void wstage_kernel(const float* __restrict__ W) {
    int idx = blockIdx.x * blockDim.x + threadIdx.x;   // 8*512*36 = 147456
    if (idx >= NSTAGES * 512 * SBW) return;
    int kt = idx % SBW;
    int rest = idx / SBW;
    int n = rest & 511, s = rest >> 9;
    uint32_t v = 0;
    if (kt < 32) {
        const float* p = W + n * KTOT + s * KSTAGE + 2 * kt;
        v = packh2(p[0], p[1]);
    }
    g_wst[idx] = v;
}

// ---------------- fused kernel ----------------
// Grid 1024: CTA = (b,t). Tile 64(m=h) x 512(n=o), K=512 in 8 stages of 64.
// 512 threads = 16 warps (2m x 8n), warp tile 32x64, per-thread 64 fp32 acc.

// smem layout
constexpr int SM_MBAR = 0;                 // 2 mbarriers @ 0, 8
constexpr int F_RS   = 16;                 // float indices from here
constexpr int F_RQ   = F_RS + 512;
constexpr int F_MU   = F_RQ + 512;
constexpr int F_RSTD = F_MU + 64;
constexpr int F_LW   = F_RSTD + 64;
constexpr int F_LB   = F_LW + 512;
constexpr int F_SBIA = F_LB + 512;         // ends float 2704
constexpr int SM_A   = 12288;              // 2 x 8704
constexpr int SM_B   = SM_A + 2 * A_STAGE_BYTES;        // 29696
constexpr int SMEM_BYTES = SM_B + 2 * B_STAGE_BYTES;    // 177152

__global__ __launch_bounds__(512, 1)
void fused_kernel(const float* __restrict__ x,
                  const float* __restrict__ prelu_a,
                  const float* __restrict__ lnw,
                  const float* __restrict__ lnb,
                  float* __restrict__ out) {
    extern __shared__ float smf[];
    const uint32_t smb = smem_u32(smf);
    const int tid = threadIdx.x;
    const int b = blockIdx.x >> 8;
    const int t = blockIdx.x & 255;

    // epilogue constants
    smf[F_LW + tid]   = lnw[tid];
    smf[F_LB + tid]   = lnb[tid];
    smf[F_SBIA + tid] = g_sbias[b * 512 + tid];

    if (tid == 0) { mbar_init(smb + SM_MBAR, 1); mbar_init(smb + SM_MBAR + 8, 1); }
    __syncthreads();

    const int lane = tid & 31, w = tid >> 5;
    const int wm = w >> 3, wn = w & 7;
    const int qid = lane >> 2, tig = lane & 3;
    const int akt = tid >> 4;            // 0..31  (k-pair row)
    const int am0 = (tid & 15) * 4;      // m quad

    // ---- A load split: LDG early, pack+STS late ----
    const float* xa_base = x + (size_t)b * 512 * 16384 + t * 64 + am0;
    auto ldgA = [&](int s, float4& f0, float4& f1) {
        const float* p = xa_base + (size_t)(s * KSTAGE + 2 * akt) * 16384;
        f0 = *(const float4*)p;
        f1 = *(const float4*)(p + 16384);
    };
    auto stsA = [&](int buf, const float4& f0, const float4& f1) {
        uint32_t w0 = packh2(f0.x, f1.x);
        uint32_t w1 = packh2(f0.y, f1.y);
        uint32_t w2 = packh2(f0.z, f1.z);
        uint32_t w3 = packh2(f0.w, f1.w);
        uint32_t dst = smb + SM_A + buf * A_STAGE_BYTES + (akt * SAW + am0) * 4;
        asm volatile("st.shared.v4.b32 [%0], {%1,%2,%3,%4};"
                     :: "r"(dst), "r"(w0), "r"(w1), "r"(w2), "r"(w3));
    };
    auto loadB = [&](int s, int buf) {
        if (tid == 0) {
            uint32_t mb = smb + SM_MBAR + 8 * buf;
            mbar_expect_tx(mb, B_STAGE_BYTES);
            bulk_g2s(smb + SM_B + buf * B_STAGE_BYTES,
                     g_wst + s * 512 * SBW, B_STAGE_BYTES, mb);
        }
    };

    float acc[2][8][4];
#pragma unroll
    for (int mt = 0; mt < 2; ++mt)
#pragma unroll
        for (int nt = 0; nt < 8; ++nt)
#pragma unroll
            for (int r = 0; r < 4; ++r) acc[mt][nt][r] = 0.f;

    // prologue: stages 0,1
    {
        float4 f0, f1;
        ldgA(0, f0, f1); stsA(0, f0, f1);
        ldgA(1, f0, f1); stsA(1, f0, f1);
    }
    loadB(0, 0);
    loadB(1, 1);
    int ph[2] = {0, 0};

    float4 pf0, pf1;   // A prefetch registers
    for (int s = 0; s < NSTAGES; ++s) {
        const int buf = s & 1;
        mbar_wait(smb + SM_MBAR + 8 * buf, ph[buf]);
        ph[buf] ^= 1;
        __syncthreads();   // A(s) STS visible to all; B(s) arrival broadcast

        if (s + 2 < NSTAGES) ldgA(s + 2, pf0, pf1);   // issue early, consume after compute

        const uint32_t* A2 = (const uint32_t*)((const char*)smf + SM_A + buf * A_STAGE_BYTES);
        const uint32_t* B2 = (const uint32_t*)((const char*)smf + SM_B + buf * B_STAGE_BYTES);

#pragma unroll
        for (int c4 = 0; c4 < 4; ++c4) {
            const int kt0 = c4 * 8;
            uint32_t a[2][4];
#pragma unroll
            for (int mt = 0; mt < 2; ++mt) {
                const int m0 = wm * 32 + mt * 16 + qid;
                a[mt][0] = A2[(kt0 + tig) * SAW + m0];
                a[mt][1] = A2[(kt0 + tig) * SAW + m0 + 8];
                a[mt][2] = A2[(kt0 + 4 + tig) * SAW + m0];
                a[mt][3] = A2[(kt0 + 4 + tig) * SAW + m0 + 8];
            }
#pragma unroll
            for (int nt = 0; nt < 8; ++nt) {
                const int n = wn * 64 + nt * 8 + qid;
                uint32_t bb[2];
                bb[0] = B2[n * SBW + kt0 + tig];
                bb[1] = B2[n * SBW + kt0 + 4 + tig];
                mma_f16(acc[0][nt], a[0], bb);
                mma_f16(acc[1][nt], a[1], bb);
            }
        }
        __syncthreads();   // all warps done reading buf
        if (s + 2 < NSTAGES) {
            stsA(buf, pf0, pf1);
            loadB(s + 2, buf);
        }
    }

    // ---------------- epilogue: +sbias, PReLU, LayerNorm, residual ----------------
    const float pa = prelu_a[0];

    float srow[4] = {0.f, 0.f, 0.f, 0.f};
    float qrow[4] = {0.f, 0.f, 0.f, 0.f};
#pragma unroll
    for (int mt = 0; mt < 2; ++mt)
#pragma unroll
        for (int nt = 0; nt < 8; ++nt)
#pragma unroll
            for (int r = 0; r < 4; ++r) {
                const int half = r >> 1;
                const int n = wn * 64 + nt * 8 + tig * 2 + (r & 1);
                float v = acc[mt][nt][r] + smf[F_SBIA + n];
                v = (v >= 0.f) ? v : pa * v;
                acc[mt][nt][r] = v;
                srow[mt * 2 + half] += v;
                qrow[mt * 2 + half] += v * v;
            }
#pragma unroll
    for (int off = 1; off <= 2; off <<= 1)
#pragma unroll
        for (int i = 0; i < 4; ++i) {
            srow[i] += __shfl_xor_sync(0xffffffffu, srow[i], off);
            qrow[i] += __shfl_xor_sync(0xffffffffu, qrow[i], off);
        }
    if (tig == 0) {
#pragma unroll
        for (int i = 0; i < 4; ++i) {
            const int rrow = wm * 32 + (i >> 1) * 16 + (i & 1) * 8 + qid;
            smf[F_RS + rrow * 8 + wn] = srow[i];
            smf[F_RQ + rrow * 8 + wn] = qrow[i];
        }
    }
    __syncthreads();
    if (tid < 64) {
        float s8 = 0.f, q8 = 0.f;
#pragma unroll
        for (int j = 0; j < 8; ++j) {
            s8 += smf[F_RS + tid * 8 + j];
            q8 += smf[F_RQ + tid * 8 + j];
        }
        const float mu = s8 * (1.f / 512.f);
        float var = q8 * (1.f / 512.f) - mu * mu;
        var = fmaxf(var, 0.f);
        smf[F_MU + tid] = mu;
        smf[F_RSTD + tid] = rsqrtf(var + 1e-8f);
    }
    __syncthreads();

    float mu4[4], rs4[4];
#pragma unroll
    for (int i = 0; i < 4; ++i) {
        const int rrow = wm * 32 + (i >> 1) * 16 + (i & 1) * 8 + qid;
        mu4[i] = smf[F_MU + rrow];
        rs4[i] = smf[F_RSTD + rrow];
    }

    const size_t base = ((size_t)b * 512 * 256 + t) * 64;
#pragma unroll
    for (int mt = 0; mt < 2; ++mt)
#pragma unroll
        for (int nt = 0; nt < 8; ++nt)
#pragma unroll
            for (int r = 0; r < 4; ++r) {
                const int i = mt * 2 + (r >> 1);
                const int rrow = wm * 32 + mt * 16 + (r >> 1) * 8 + qid;
                const int n = wn * 64 + nt * 8 + tig * 2 + (r & 1);
                const size_t gi = base + (size_t)n * 16384 + rrow;
                out[gi] = (acc[mt][nt][r] - mu4[i]) * rs4[i] * smf[F_LW + n] +
                          smf[F_LB + n] + __ldg(x + gi);
            }
}

// ---------------- launch ----------------

extern "C" void kernel_launch(void* const* d_in, const int* in_sizes, int n_in,
                              void* d_out, int out_size) {
    (void)in_sizes; (void)n_in; (void)out_size;
    const float* x      = (const float*)d_in[0];
    const float* s      = (const float*)d_in[1];
    // d_in[2..4]: prelu1_a, ln1_w, ln1_b — dead code in the reference
    const float* W      = (const float*)d_in[5];
    const float* bias   = (const float*)d_in[6];
    const float* prelu2 = (const float*)d_in[7];
    const float* ln2w   = (const float*)d_in[8];
    const float* ln2b   = (const float*)d_in[9];
    float* out = (float*)d_out;

    cudaFuncSetAttribute(fused_kernel,
                         cudaFuncAttributeMaxDynamicSharedMemorySize, SMEM_BYTES);

    sbias_kernel<<<256, 256>>>(s, W, bias);
    wstage_kernel<<<576, 256>>>(W);
    fused_kernel<<<1024, 512, SMEM_BYTES>>>(x, prelu2, ln2w, ln2b, out);
}

// round 7
// speedup vs baseline: 2.3535x; 1.0308x over previous
#include <cuda_runtime.h>
#include <cuda_fp16.h>
#include <cstdint>

#define DEV_INLINE __device__ __forceinline__

constexpr int KTOT = 768;
constexpr int NSTAGES = 8, KSTAGE = 64;          // K = 512
constexpr int SBW = 36;                           // u32 words per B row (32 kt + 4 pad)
constexpr int SAW = 68;                           // u32 words per A k-row (64 m + 4 pad)
constexpr int B_STAGE_BYTES = 512 * SBW * 4;      // 73728
constexpr int A_STAGE_BYTES = 32 * SAW * 4;       // 8704

// static device scratch
__device__ float g_sbias[4 * 512];
__device__ __align__(128) uint32_t g_wst[NSTAGES * 512 * SBW];  // fp16-packed, padded W stages

// ---------------- PTX helpers ----------------

DEV_INLINE uint32_t smem_u32(const void* p) {
    uint32_t a;
    asm("{ .reg .u64 t; cvta.to.shared.u64 t, %1; cvt.u32.u64 %0, t; }" : "=r"(a) : "l"(p));
    return a;
}
DEV_INLINE void mbar_init(uint32_t a, uint32_t cnt) {
    asm volatile("mbarrier.init.shared.b64 [%0], %1;" :: "r"(a), "r"(cnt) : "memory");
}
DEV_INLINE void mbar_expect_tx(uint32_t a, uint32_t bytes) {
    asm volatile("mbarrier.arrive.expect_tx.shared.b64 _, [%0], %1;" :: "r"(a), "r"(bytes) : "memory");
}
DEV_INLINE void mbar_wait(uint32_t a, uint32_t parity) {
    asm volatile(
        "{ .reg .pred P;\n"
        "W_%=:\n"
        " mbarrier.try_wait.parity.acquire.cta.shared::cta.b64 P, [%0], %1, 0x989680;\n"
        " @P bra.uni D_%=;\n"
        " bra.uni W_%=;\n"
        "D_%=:\n}"
        :: "r"(a), "r"(parity) : "memory");
}
DEV_INLINE void bulk_g2s(uint32_t dst, const void* src, uint32_t bytes, uint32_t mbar) {
    asm volatile(
        "cp.async.bulk.shared::cluster.global.mbarrier::complete_tx::bytes [%0], [%1], %2, [%3];"
        :: "r"(dst), "l"(src), "r"(bytes), "r"(mbar) : "memory");
}
DEV_INLINE void mma_f16(float* d, const uint32_t* a, const uint32_t* b) {
    asm volatile(
        "mma.sync.aligned.m16n8k16.row.col.f32.f16.f16.f32 "
        "{%0,%1,%2,%3}, {%4,%5,%6,%7}, {%8,%9}, {%0,%1,%2,%3};\n"
        : "+f"(d[0]), "+f"(d[1]), "+f"(d[2]), "+f"(d[3])
        : "r"(a[0]), "r"(a[1]), "r"(a[2]), "r"(a[3]), "r"(b[0]), "r"(b[1]));
}
DEV_INLINE uint32_t packh2(float lo, float hi) {
    __half2 h = __floats2half2_rn(lo, hi);
    return *reinterpret_cast<uint32_t*>(&h);
}

// ---------------- merged prologue kernel ----------------
// blocks [0,576): W -> fp16-packed padded stage image; blocks [576,832): sbias GEMV

__global__ void prep_kernel(const float* __restrict__ s,
                            const float* __restrict__ W,
                            const float* __restrict__ bias) {
    if (blockIdx.x < 576) {
        int idx = blockIdx.x * 256 + threadIdx.x;   // 8*512*36 = 147456
        if (idx >= NSTAGES * 512 * SBW) return;
        int kt = idx % SBW;
        int rest = idx / SBW;
        int n = rest & 511, st = rest >> 9;
        uint32_t v = 0;
        if (kt < 32) {
            const float* p = W + n * KTOT + st * KSTAGE + 2 * kt;
            v = packh2(p[0], p[1]);
        }
        g_wst[idx] = v;
    } else {
        int gw = ((blockIdx.x - 576) * 256 + threadIdx.x) >> 5;   // 2048 warps: (b,o)
        int lane = threadIdx.x & 31;
        int b = gw >> 9, o = gw & 511;
        const float* wrow = W + o * KTOT + 512;
        const float* srow = s + b * 256;
        float acc = 0.f;
#pragma unroll
        for (int j = 0; j < 8; ++j) acc += srow[lane + 32 * j] * wrow[lane + 32 * j];
#pragma unroll
        for (int off = 16; off; off >>= 1) acc += __shfl_xor_sync(0xffffffffu, acc, off);
        if (lane == 0) g_sbias[b * 512 + o] = acc + bias[o];
    }
}

// ---------------- fused kernel ----------------
// Grid 1024: CTA = (b,t). Tile 64(m=h) x 512(n=o), K=512 in 8 stages of 64.
// 512 threads = 16 warps (2m x 8n), warp tile 32x64, per-thread 64 fp32 acc.

// smem layout
constexpr int SM_MBAR = 0;                 // 2 mbarriers @ 0, 8
constexpr int F_RS   = 16;                 // float indices from here
constexpr int F_RQ   = F_RS + 512;
constexpr int F_MU   = F_RQ + 512;
constexpr int F_RSTD = F_MU + 64;
constexpr int F_LW   = F_RSTD + 64;
constexpr int F_LB   = F_LW + 512;
constexpr int F_SBIA = F_LB + 512;         // ends float 2704
constexpr int SM_A   = 12288;              // 2 x 8704
constexpr int SM_B   = SM_A + 2 * A_STAGE_BYTES;        // 29696
constexpr int SMEM_BYTES = SM_B + 2 * B_STAGE_BYTES;    // 177152
constexpr int F_STAGE = SM_B >> 2;         // epilogue staging: [512 n][72] floats = 147456 B

__global__ __launch_bounds__(512, 1)
void fused_kernel(const float* __restrict__ x,
                  const float* __restrict__ prelu_a,
                  const float* __restrict__ lnw,
                  const float* __restrict__ lnb,
                  float* __restrict__ out) {
    extern __shared__ float smf[];
    const uint32_t smb = smem_u32(smf);
    const int tid = threadIdx.x;
    const int b = blockIdx.x >> 8;
    const int t = blockIdx.x & 255;

    // epilogue constants
    smf[F_LW + tid]   = lnw[tid];
    smf[F_LB + tid]   = lnb[tid];
    smf[F_SBIA + tid] = g_sbias[b * 512 + tid];

    if (tid == 0) { mbar_init(smb + SM_MBAR, 1); mbar_init(smb + SM_MBAR + 8, 1); }
    __syncthreads();

    const int lane = tid & 31, w = tid >> 5;
    const int wm = w >> 3, wn = w & 7;
    const int qid = lane >> 2, tig = lane & 3;
    const int akt = tid >> 4;            // 0..31  (k-pair row)
    const int am0 = (tid & 15) * 4;      // m quad

    // ---- A load split: LDG early, pack+STS late ----
    const float* xa_base = x + (size_t)b * 512 * 16384 + t * 64 + am0;
    auto ldgA = [&](int s, float4& f0, float4& f1) {
        const float* p = xa_base + (size_t)(s * KSTAGE + 2 * akt) * 16384;
        f0 = *(const float4*)p;
        f1 = *(const float4*)(p + 16384);
    };
    auto stsA = [&](int buf, const float4& f0, const float4& f1) {
        uint32_t w0 = packh2(f0.x, f1.x);
        uint32_t w1 = packh2(f0.y, f1.y);
        uint32_t w2 = packh2(f0.z, f1.z);
        uint32_t w3 = packh2(f0.w, f1.w);
        uint32_t dst = smb + SM_A + buf * A_STAGE_BYTES + (akt * SAW + am0) * 4;
        asm volatile("st.shared.v4.b32 [%0], {%1,%2,%3,%4};"
                     :: "r"(dst), "r"(w0), "r"(w1), "r"(w2), "r"(w3));
    };
    auto loadB = [&](int s, int buf) {
        if (tid == 0) {
            uint32_t mb = smb + SM_MBAR + 8 * buf;
            mbar_expect_tx(mb, B_STAGE_BYTES);
            bulk_g2s(smb + SM_B + buf * B_STAGE_BYTES,
                     g_wst + s * 512 * SBW, B_STAGE_BYTES, mb);
        }
    };

    float acc[2][8][4];
#pragma unroll
    for (int mt = 0; mt < 2; ++mt)
#pragma unroll
        for (int nt = 0; nt < 8; ++nt)
#pragma unroll
            for (int r = 0; r < 4; ++r) acc[mt][nt][r] = 0.f;

    // prologue: stages 0,1
    {
        float4 f0, f1;
        ldgA(0, f0, f1); stsA(0, f0, f1);
        ldgA(1, f0, f1); stsA(1, f0, f1);
    }
    loadB(0, 0);
    loadB(1, 1);
    int ph[2] = {0, 0};

    float4 pf0, pf1;   // A prefetch registers
    for (int s = 0; s < NSTAGES; ++s) {
        const int buf = s & 1;
        mbar_wait(smb + SM_MBAR + 8 * buf, ph[buf]);
        ph[buf] ^= 1;
        __syncthreads();   // A(s) STS visible to all; B(s) arrival broadcast

        if (s + 2 < NSTAGES) ldgA(s + 2, pf0, pf1);   // issue early, consume after compute

        const uint32_t* A2 = (const uint32_t*)((const char*)smf + SM_A + buf * A_STAGE_BYTES);
        const uint32_t* B2 = (const uint32_t*)((const char*)smf + SM_B + buf * B_STAGE_BYTES);

#pragma unroll
        for (int c4 = 0; c4 < 4; ++c4) {
            const int kt0 = c4 * 8;
            uint32_t a[2][4];
#pragma unroll
            for (int mt = 0; mt < 2; ++mt) {
                const int m0 = wm * 32 + mt * 16 + qid;
                a[mt][0] = A2[(kt0 + tig) * SAW + m0];
                a[mt][1] = A2[(kt0 + tig) * SAW + m0 + 8];
                a[mt][2] = A2[(kt0 + 4 + tig) * SAW + m0];
                a[mt][3] = A2[(kt0 + 4 + tig) * SAW + m0 + 8];
            }
#pragma unroll
            for (int nt = 0; nt < 8; ++nt) {
                const int n = wn * 64 + nt * 8 + qid;
                uint32_t bb[2];
                bb[0] = B2[n * SBW + kt0 + tig];
                bb[1] = B2[n * SBW + kt0 + 4 + tig];
                mma_f16(acc[0][nt], a[0], bb);
                mma_f16(acc[1][nt], a[1], bb);
            }
        }
        __syncthreads();   // all warps done reading buf
        if (s + 2 < NSTAGES) {
            stsA(buf, pf0, pf1);
            loadB(s + 2, buf);
        }
    }

    // ---------------- epilogue ----------------
    // Phase 1: +sbias, PReLU; stage v into smem [n][72]; accumulate row stats.
    const float pa = prelu_a[0];

    float srow[4] = {0.f, 0.f, 0.f, 0.f};
    float qrow[4] = {0.f, 0.f, 0.f, 0.f};
#pragma unroll
    for (int mt = 0; mt < 2; ++mt)
#pragma unroll
        for (int nt = 0; nt < 8; ++nt)
#pragma unroll
            for (int r = 0; r < 4; ++r) {
                const int half = r >> 1;
                const int n = wn * 64 + nt * 8 + tig * 2 + (r & 1);
                const int rrow = wm * 32 + mt * 16 + half * 8 + qid;
                float v = acc[mt][nt][r] + smf[F_SBIA + n];
                v = (v >= 0.f) ? v : pa * v;
                smf[F_STAGE + n * 72 + rrow] = v;
                srow[mt * 2 + half] += v;
                qrow[mt * 2 + half] += v * v;
            }
#pragma unroll
    for (int off = 1; off <= 2; off <<= 1)
#pragma unroll
        for (int i = 0; i < 4; ++i) {
            srow[i] += __shfl_xor_sync(0xffffffffu, srow[i], off);
            qrow[i] += __shfl_xor_sync(0xffffffffu, qrow[i], off);
        }
    if (tig == 0) {
#pragma unroll
        for (int i = 0; i < 4; ++i) {
            const int rrow = wm * 32 + (i >> 1) * 16 + (i & 1) * 8 + qid;
            smf[F_RS + rrow * 8 + wn] = srow[i];
            smf[F_RQ + rrow * 8 + wn] = qrow[i];
        }
    }
    __syncthreads();
    if (tid < 64) {
        float s8 = 0.f, q8 = 0.f;
#pragma unroll
        for (int j = 0; j < 8; ++j) {
            s8 += smf[F_RS + tid * 8 + j];
            q8 += smf[F_RQ + tid * 8 + j];
        }
        const float mu = s8 * (1.f / 512.f);
        float var = q8 * (1.f / 512.f) - mu * mu;
        var = fmaxf(var, 0.f);
        smf[F_MU + tid] = mu;
        smf[F_RSTD + tid] = rsqrtf(var + 1e-8f);
    }
    __syncthreads();

    // Phase 2: coalesced normalize + residual + store. Warp w owns n = i*16 + w.
    const float mu0 = smf[F_MU + lane],      rs0 = smf[F_RSTD + lane];
    const float mu1 = smf[F_MU + lane + 32], rs1 = smf[F_RSTD + lane + 32];
    const size_t base = ((size_t)b * 512 * 256 + t) * 64;
#pragma unroll 4
    for (int i = 0; i < 32; ++i) {
        const int n = i * 16 + w;
        const float lw = smf[F_LW + n], lb = smf[F_LB + n];
        const float v0 = smf[F_STAGE + n * 72 + lane];
        const float v1 = smf[F_STAGE + n * 72 + lane + 32];
        const size_t gi = base + (size_t)n * 16384 + lane;
        out[gi]      = (v0 - mu0) * rs0 * lw + lb + x[gi];
        out[gi + 32] = (v1 - mu1) * rs1 * lw + lb + x[gi + 32];
    }
}

// ---------------- launch ----------------

extern "C" void kernel_launch(void* const* d_in, const int* in_sizes, int n_in,
                              void* d_out, int out_size) {
    (void)in_sizes; (void)n_in; (void)out_size;
    const float* x      = (const float*)d_in[0];
    const float* s      = (const float*)d_in[1];
    // d_in[2..4]: prelu1_a, ln1_w, ln1_b — dead code in the reference
    const float* W      = (const float*)d_in[5];
    const float* bias   = (const float*)d_in[6];
    const float* prelu2 = (const float*)d_in[7];
    const float* ln2w   = (const float*)d_in[8];
    const float* ln2b   = (const float*)d_in[9];
    float* out = (float*)d_out;

    cudaFuncSetAttribute(fused_kernel,
                         cudaFuncAttributeMaxDynamicSharedMemorySize, SMEM_BYTES);

    prep_kernel<<<832, 256>>>(s, W, bias);
    fused_kernel<<<1024, 512, SMEM_BYTES>>>(x, prelu2, ln2w, ln2b, out);
}

// round 8
// speedup vs baseline: 2.5468x; 1.0821x over previous
#include <cuda_runtime.h>
#include <cuda_fp16.h>
#include <cstdint>

#define DEV_INLINE __device__ __forceinline__

constexpr int KTOT = 768;
constexpr int NSTAGES = 8, KSTAGE = 64;          // K = 512
constexpr int SBW = 36;                           // u32 words per B row (32 kt + 4 pad)
constexpr int SAW = 72;                           // u32 words per A k-row (64 m + 8 pad) -> conflict-free
constexpr int B_STAGE_BYTES = 512 * SBW * 4;      // 73728
constexpr int A_STAGE_BYTES = 32 * SAW * 4;       // 9216

// static device scratch
__device__ float g_sbias[4 * 512];
__device__ __align__(128) uint32_t g_wst[NSTAGES * 512 * SBW];  // fp16-packed, padded W stages

// ---------------- PTX helpers ----------------

DEV_INLINE uint32_t smem_u32(const void* p) {
    uint32_t a;
    asm("{ .reg .u64 t; cvta.to.shared.u64 t, %1; cvt.u32.u64 %0, t; }" : "=r"(a) : "l"(p));
    return a;
}
DEV_INLINE void mbar_init(uint32_t a, uint32_t cnt) {
    asm volatile("mbarrier.init.shared.b64 [%0], %1;" :: "r"(a), "r"(cnt) : "memory");
}
DEV_INLINE void mbar_expect_tx(uint32_t a, uint32_t bytes) {
    asm volatile("mbarrier.arrive.expect_tx.shared.b64 _, [%0], %1;" :: "r"(a), "r"(bytes) : "memory");
}
DEV_INLINE void mbar_wait(uint32_t a, uint32_t parity) {
    asm volatile(
        "{ .reg .pred P;\n"
        "W_%=:\n"
        " mbarrier.try_wait.parity.acquire.cta.shared::cta.b64 P, [%0], %1, 0x989680;\n"
        " @P bra.uni D_%=;\n"
        " bra.uni W_%=;\n"
        "D_%=:\n}"
        :: "r"(a), "r"(parity) : "memory");
}
DEV_INLINE void bulk_g2s(uint32_t dst, const void* src, uint32_t bytes, uint32_t mbar) {
    asm volatile(
        "cp.async.bulk.shared::cluster.global.mbarrier::complete_tx::bytes [%0], [%1], %2, [%3];"
        :: "r"(dst), "l"(src), "r"(bytes), "r"(mbar) : "memory");
}
DEV_INLINE void mma_f16(float* d, const uint32_t* a, uint32_t b0, uint32_t b1) {
    asm volatile(
        "mma.sync.aligned.m16n8k16.row.col.f32.f16.f16.f32 "
        "{%0,%1,%2,%3}, {%4,%5,%6,%7}, {%8,%9}, {%0,%1,%2,%3};\n"
        : "+f"(d[0]), "+f"(d[1]), "+f"(d[2]), "+f"(d[3])
        : "r"(a[0]), "r"(a[1]), "r"(a[2]), "r"(a[3]), "r"(b0), "r"(b1));
}
DEV_INLINE void ldsm_x4(uint32_t& r0, uint32_t& r1, uint32_t& r2, uint32_t& r3, uint32_t addr) {
    asm volatile("ldmatrix.sync.aligned.m8n8.x4.shared.b16 {%0,%1,%2,%3}, [%4];"
                 : "=r"(r0), "=r"(r1), "=r"(r2), "=r"(r3) : "r"(addr));
}
DEV_INLINE uint32_t packh2(float lo, float hi) {
    __half2 h = __floats2half2_rn(lo, hi);
    return *reinterpret_cast<uint32_t*>(&h);
}

// ---------------- merged prologue kernel ----------------
// blocks [0,576): W -> fp16-packed padded stage image; blocks [576,832): sbias GEMV

__global__ void prep_kernel(const float* __restrict__ s,
                            const float* __restrict__ W,
                            const float* __restrict__ bias) {
    if (blockIdx.x < 576) {
        int idx = blockIdx.x * 256 + threadIdx.x;   // 8*512*36 = 147456
        if (idx >= NSTAGES * 512 * SBW) return;
        int kt = idx % SBW;
        int rest = idx / SBW;
        int n = rest & 511, st = rest >> 9;
        uint32_t v = 0;
        if (kt < 32) {
            const float* p = W + n * KTOT + st * KSTAGE + 2 * kt;
            v = packh2(p[0], p[1]);
        }
        g_wst[idx] = v;
    } else {
        int gw = ((blockIdx.x - 576) * 256 + threadIdx.x) >> 5;   // 2048 warps: (b,o)
        int lane = threadIdx.x & 31;
        int b = gw >> 9, o = gw & 511;
        const float* wrow = W + o * KTOT + 512;
        const float* srow = s + b * 256;
        float acc = 0.f;
#pragma unroll
        for (int j = 0; j < 8; ++j) acc += srow[lane + 32 * j] * wrow[lane + 32 * j];
#pragma unroll
        for (int off = 16; off; off >>= 1) acc += __shfl_xor_sync(0xffffffffu, acc, off);
        if (lane == 0) g_sbias[b * 512 + o] = acc + bias[o];
    }
}

// ---------------- fused kernel ----------------
// Grid 1024: CTA = (b,t). Tile 64(m=h) x 512(n=o), K=512 in 8 stages of 64.
// 512 threads = 16 warps (2m x 8n), warp tile 32x64, per-thread 64 fp32 acc.

// smem layout
constexpr int SM_MBAR = 0;                 // 2 mbarriers @ 0, 8
constexpr int F_RS   = 16;                 // float indices from here
constexpr int F_RQ   = F_RS + 512;
constexpr int F_MU   = F_RQ + 512;
constexpr int F_RSTD = F_MU + 64;
constexpr int F_LW   = F_RSTD + 64;
constexpr int F_LB   = F_LW + 512;
constexpr int F_SBIA = F_LB + 512;         // ends float 2704
constexpr int SM_A   = 12288;              // 2 x 9216
constexpr int SM_B   = SM_A + 2 * A_STAGE_BYTES;        // 30720
constexpr int SMEM_BYTES = SM_B + 2 * B_STAGE_BYTES;    // 178176
constexpr int F_STAGE = SM_B >> 2;         // epilogue staging: [512 n][72] floats = 147456 B

__global__ __launch_bounds__(512, 1)
void fused_kernel(const float* __restrict__ x,
                  const float* __restrict__ prelu_a,
                  const float* __restrict__ lnw,
                  const float* __restrict__ lnb,
                  float* __restrict__ out) {
    extern __shared__ float smf[];
    const uint32_t smb = smem_u32(smf);
    const int tid = threadIdx.x;
    const int b = blockIdx.x >> 8;
    const int t = blockIdx.x & 255;

    // epilogue constants
    smf[F_LW + tid]   = lnw[tid];
    smf[F_LB + tid]   = lnb[tid];
    smf[F_SBIA + tid] = g_sbias[b * 512 + tid];

    if (tid == 0) { mbar_init(smb + SM_MBAR, 1); mbar_init(smb + SM_MBAR + 8, 1); }
    __syncthreads();

    const int lane = tid & 31, w = tid >> 5;
    const int wm = w >> 3, wn = w & 7;
    const int qid = lane >> 2, tig = lane & 3;
    const int akt = tid >> 4;            // 0..31  (k-pair row)
    const int am0 = (tid & 15) * 4;      // m quad

    // B ldmatrix per-lane row offset: lanes 0-15 -> n-octet 0 (k0/k8 chunks),
    // lanes 16-31 -> n-octet 1. row = (lane>>4)*8 + (lane&7), chunk = (lane>>3)&1.
    const uint32_t b_lane_off =
        (uint32_t)((((lane >> 4) * 8 + (lane & 7)) * SBW + ((lane >> 3) & 1) * 4) * 4);

    // ---- A load split: LDG early, pack+STS late ----
    const float* xa_base = x + (size_t)b * 512 * 16384 + t * 64 + am0;
    auto ldgA = [&](int s, float4& f0, float4& f1) {
        const float* p = xa_base + (size_t)(s * KSTAGE + 2 * akt) * 16384;
        f0 = *(const float4*)p;
        f1 = *(const float4*)(p + 16384);
    };
    auto stsA = [&](int buf, const float4& f0, const float4& f1) {
        uint32_t w0 = packh2(f0.x, f1.x);
        uint32_t w1 = packh2(f0.y, f1.y);
        uint32_t w2 = packh2(f0.z, f1.z);
        uint32_t w3 = packh2(f0.w, f1.w);
        uint32_t dst = smb + SM_A + buf * A_STAGE_BYTES + (akt * SAW + am0) * 4;
        asm volatile("st.shared.v4.b32 [%0], {%1,%2,%3,%4};"
                     :: "r"(dst), "r"(w0), "r"(w1), "r"(w2), "r"(w3));
    };
    auto loadB = [&](int s, int buf) {
        if (tid == 0) {
            uint32_t mb = smb + SM_MBAR + 8 * buf;
            mbar_expect_tx(mb, B_STAGE_BYTES);
            bulk_g2s(smb + SM_B + buf * B_STAGE_BYTES,
                     g_wst + s * 512 * SBW, B_STAGE_BYTES, mb);
        }
    };

    float acc[2][8][4];
#pragma unroll
    for (int mt = 0; mt < 2; ++mt)
#pragma unroll
        for (int nt = 0; nt < 8; ++nt)
#pragma unroll
            for (int r = 0; r < 4; ++r) acc[mt][nt][r] = 0.f;

    // prologue: stages 0,1
    {
        float4 f0, f1;
        ldgA(0, f0, f1); stsA(0, f0, f1);
        ldgA(1, f0, f1); stsA(1, f0, f1);
    }
    loadB(0, 0);
    loadB(1, 1);
    int ph[2] = {0, 0};

    float4 pf0, pf1;   // A prefetch registers
    for (int s = 0; s < NSTAGES; ++s) {
        const int buf = s & 1;
        if (s + 2 < NSTAGES) ldgA(s + 2, pf0, pf1);   // overlap LDG with the wait
        mbar_wait(smb + SM_MBAR + 8 * buf, ph[buf]);
        ph[buf] ^= 1;
        __syncthreads();   // A(s) STS visible to all; B(s) arrival broadcast

        const uint32_t* A2 = (const uint32_t*)((const char*)smf + SM_A + buf * A_STAGE_BYTES);
        const uint32_t bwarp = smb + SM_B + buf * B_STAGE_BYTES +
                               (uint32_t)(wn * 64 * SBW * 4) + b_lane_off;

#pragma unroll
        for (int c4 = 0; c4 < 4; ++c4) {
            const int kt0 = c4 * 8;
            uint32_t a[2][4];
#pragma unroll
            for (int mt = 0; mt < 2; ++mt) {
                const int m0 = wm * 32 + mt * 16 + qid;
                a[mt][0] = A2[(kt0 + tig) * SAW + m0];
                a[mt][1] = A2[(kt0 + tig) * SAW + m0 + 8];
                a[mt][2] = A2[(kt0 + 4 + tig) * SAW + m0];
                a[mt][3] = A2[(kt0 + 4 + tig) * SAW + m0 + 8];
            }
#pragma unroll
            for (int np = 0; np < 4; ++np) {          // pairs of n-octets
                uint32_t b0, b1, b2, b3;
                ldsm_x4(b0, b1, b2, b3,
                        bwarp + (uint32_t)(np * 16 * SBW * 4 + kt0 * 4));
                mma_f16(acc[0][np * 2],     a[0], b0, b1);
                mma_f16(acc[1][np * 2],     a[1], b0, b1);
                mma_f16(acc[0][np * 2 + 1], a[0], b2, b3);
                mma_f16(acc[1][np * 2 + 1], a[1], b2, b3);
            }
        }
        __syncthreads();   // all warps done reading buf
        if (s + 2 < NSTAGES) {
            stsA(buf, pf0, pf1);
            loadB(s + 2, buf);
        }
    }

    // ---------------- epilogue ----------------
    // Phase 1: +sbias, PReLU; stage v into smem [n][72]; accumulate row stats.
    const float pa = prelu_a[0];

    float srow[4] = {0.f, 0.f, 0.f, 0.f};
    float qrow[4] = {0.f, 0.f, 0.f, 0.f};
#pragma unroll
    for (int mt = 0; mt < 2; ++mt)
#pragma unroll
        for (int nt = 0; nt < 8; ++nt)
#pragma unroll
            for (int r = 0; r < 4; ++r) {
                const int half = r >> 1;
                const int n = wn * 64 + nt * 8 + tig * 2 + (r & 1);
                const int rrow = wm * 32 + mt * 16 + half * 8 + qid;
                float v = acc[mt][nt][r] + smf[F_SBIA + n];
                v = (v >= 0.f) ? v : pa * v;
                smf[F_STAGE + n * 72 + rrow] = v;
                srow[mt * 2 + half] += v;
                qrow[mt * 2 + half] += v * v;
            }
#pragma unroll
    for (int off = 1; off <= 2; off <<= 1)
#pragma unroll
        for (int i = 0; i < 4; ++i) {
            srow[i] += __shfl_xor_sync(0xffffffffu, srow[i], off);
            qrow[i] += __shfl_xor_sync(0xffffffffu, qrow[i], off);
        }
    if (tig == 0) {
#pragma unroll
        for (int i = 0; i < 4; ++i) {
            const int rrow = wm * 32 + (i >> 1) * 16 + (i & 1) * 8 + qid;
            smf[F_RS + rrow * 8 + wn] = srow[i];
            smf[F_RQ + rrow * 8 + wn] = qrow[i];
        }
    }
    __syncthreads();
    if (tid < 64) {
        float s8 = 0.f, q8 = 0.f;
#pragma unroll
        for (int j = 0; j < 8; ++j) {
            s8 += smf[F_RS + tid * 8 + j];
            q8 += smf[F_RQ + tid * 8 + j];
        }
        const float mu = s8 * (1.f / 512.f);
        float var = q8 * (1.f / 512.f) - mu * mu;
        var = fmaxf(var, 0.f);
        smf[F_MU + tid] = mu;
        smf[F_RSTD + tid] = rsqrtf(var + 1e-8f);
    }
    __syncthreads();

    // Phase 2: coalesced normalize + residual + store. Warp w owns n = i*16 + w.
    const float mu0 = smf[F_MU + lane],      rs0 = smf[F_RSTD + lane];
    const float mu1 = smf[F_MU + lane + 32], rs1 = smf[F_RSTD + lane + 32];
    const size_t base = ((size_t)b * 512 * 256 + t) * 64;
#pragma unroll 4
    for (int i = 0; i < 32; ++i) {
        const int n = i * 16 + w;
        const float lw = smf[F_LW + n], lb = smf[F_LB + n];
        const float v0 = smf[F_STAGE + n * 72 + lane];
        const float v1 = smf[F_STAGE + n * 72 + lane + 32];
        const size_t gi = base + (size_t)n * 16384 + lane;
        out[gi]      = (v0 - mu0) * rs0 * lw + lb + x[gi];
        out[gi + 32] = (v1 - mu1) * rs1 * lw + lb + x[gi + 32];
    }
}

// ---------------- launch ----------------

extern "C" void kernel_launch(void* const* d_in, const int* in_sizes, int n_in,
                              void* d_out, int out_size) {
    (void)in_sizes; (void)n_in; (void)out_size;
    const float* x      = (const float*)d_in[0];
    const float* s      = (const float*)d_in[1];
    // d_in[2..4]: prelu1_a, ln1_w, ln1_b — dead code in the reference
    const float* W      = (const float*)d_in[5];
    const float* bias   = (const float*)d_in[6];
    const float* prelu2 = (const float*)d_in[7];
    const float* ln2w   = (const float*)d_in[8];
    const float* ln2b   = (const float*)d_in[9];
    float* out = (float*)d_out;

    cudaFuncSetAttribute(fused_kernel,
                         cudaFuncAttributeMaxDynamicSharedMemorySize, SMEM_BYTES);

    prep_kernel<<<832, 256>>>(s, W, bias);
    fused_kernel<<<1024, 512, SMEM_BYTES>>>(x, prelu2, ln2w, ln2b, out);
}

// round 10
// speedup vs baseline: 2.9518x; 1.1590x over previous
#include <cuda_runtime.h>
#include <cuda_fp16.h>
#include <cstdint>

#define DEV_INLINE __device__ __forceinline__

constexpr int KTOT = 768;
constexpr int NSTAGES = 8, KSTAGE = 64;          // K = 512
constexpr int SBW = 36;                           // u32 words per B row (32 kt + 4 pad)
constexpr int SAW = 72;                           // u32 words per A k-row (64 m + 8 pad)
constexpr int B_STAGE_BYTES = 512 * SBW * 4;      // 73728
constexpr int A_STAGE_BYTES = 32 * SAW * 4;       // 9216

// static device scratch
__device__ float g_sbias[4 * 512];
__device__ __align__(128) uint32_t g_wst[NSTAGES * 512 * SBW];  // fp16-packed, padded W stages

// ---------------- PTX helpers ----------------

DEV_INLINE uint32_t smem_u32(const void* p) {
    uint32_t a;
    asm("{ .reg .u64 t; cvta.to.shared.u64 t, %1; cvt.u32.u64 %0, t; }" : "=r"(a) : "l"(p));
    return a;
}
DEV_INLINE void mbar_init(uint32_t a, uint32_t cnt) {
    asm volatile("mbarrier.init.shared.b64 [%0], %1;" :: "r"(a), "r"(cnt) : "memory");
}
DEV_INLINE void mbar_arrive(uint32_t a) {
    asm volatile("mbarrier.arrive.release.cta.shared::cta.b64 _, [%0];" :: "r"(a) : "memory");
}
DEV_INLINE void mbar_expect_tx(uint32_t a, uint32_t bytes) {
    asm volatile("mbarrier.arrive.expect_tx.shared.b64 _, [%0], %1;" :: "r"(a), "r"(bytes) : "memory");
}
DEV_INLINE void mbar_wait(uint32_t a, uint32_t parity) {
    asm volatile(
        "{ .reg .pred P;\n"
        "W_%=:\n"
        " mbarrier.try_wait.parity.acquire.cta.shared::cta.b64 P, [%0], %1, 0x989680;\n"
        " @P bra.uni D_%=;\n"
        " bra.uni W_%=;\n"
        "D_%=:\n}"
        :: "r"(a), "r"(parity) : "memory");
}
DEV_INLINE void bulk_g2s(uint32_t dst, const void* src, uint32_t bytes, uint32_t mbar) {
    asm volatile(
        "cp.async.bulk.shared::cluster.global.mbarrier::complete_tx::bytes [%0], [%1], %2, [%3];"
        :: "r"(dst), "l"(src), "r"(bytes), "r"(mbar) : "memory");
}
DEV_INLINE void mma_f16(float* d, const uint32_t* a, uint32_t b0, uint32_t b1) {
    asm volatile(
        "mma.sync.aligned.m16n8k16.row.col.f32.f16.f16.f32 "
        "{%0,%1,%2,%3}, {%4,%5,%6,%7}, {%8,%9}, {%0,%1,%2,%3};\n"
        : "+f"(d[0]), "+f"(d[1]), "+f"(d[2]), "+f"(d[3])
        : "r"(a[0]), "r"(a[1]), "r"(a[2]), "r"(a[3]), "r"(b0), "r"(b1));
}
DEV_INLINE void ldsm_x4(uint32_t& r0, uint32_t& r1, uint32_t& r2, uint32_t& r3, uint32_t addr) {
    asm volatile("ldmatrix.sync.aligned.m8n8.x4.shared.b16 {%0,%1,%2,%3}, [%4];"
                 : "=r"(r0), "=r"(r1), "=r"(r2), "=r"(r3) : "r"(addr));
}
DEV_INLINE uint32_t packh2(float lo, float hi) {
    __half2 h = __floats2half2_rn(lo, hi);
    return *reinterpret_cast<uint32_t*>(&h);
}

// ---------------- merged prologue kernel ----------------

__global__ void prep_kernel(const float* __restrict__ s,
                            const float* __restrict__ W,
                            const float* __restrict__ bias) {
    if (blockIdx.x < 576) {
        int idx = blockIdx.x * 256 + threadIdx.x;   // 8*512*36 = 147456
        if (idx >= NSTAGES * 512 * SBW) return;
        int kt = idx % SBW;
        int rest = idx / SBW;
        int n = rest & 511, st = rest >> 9;
        uint32_t v = 0;
        if (kt < 32) {
            const float* p = W + n * KTOT + st * KSTAGE + 2 * kt;
            v = packh2(p[0], p[1]);
        }
        g_wst[idx] = v;
    } else {
        int gw = ((blockIdx.x - 576) * 256 + threadIdx.x) >> 5;   // 2048 warps: (b,o)
        int lane = threadIdx.x & 31;
        int b = gw >> 9, o = gw & 511;
        const float* wrow = W + o * KTOT + 512;
        const float* srow = s + b * 256;
        float acc = 0.f;
#pragma unroll
        for (int j = 0; j < 8; ++j) acc += srow[lane + 32 * j] * wrow[lane + 32 * j];
#pragma unroll
        for (int off = 16; off; off >>= 1) acc += __shfl_xor_sync(0xffffffffu, acc, off);
        if (lane == 0) g_sbias[b * 512 + o] = acc + bias[o];
    }
}

// ---------------- fused kernel ----------------
// Grid 1024: CTA = (b,t). Tile 64(m) x 512(n), K=512 in 8 stages of 64.
// 512 threads = 16 warps (2m x 8n). Barrier-free mainloop: mbarrier ring
// (tma[2] B-full, ardy[4] A-ready cnt512, rd[2] read-done cnt16).

// smem layout (bytes / float indices)
constexpr int MB_TMA  = 0;                 // 2 x 8B
constexpr int MB_ARDY = 16;                // 4 x 8B
constexpr int MB_RD   = 48;                // 2 x 8B
constexpr int F_RS   = 16;                 // float indices (byte 64)
constexpr int F_RQ   = F_RS + 512;
constexpr int F_MU   = F_RQ + 512;
constexpr int F_RSTD = F_MU + 64;
constexpr int F_LW   = F_RSTD + 64;
constexpr int F_LB   = F_LW + 512;
constexpr int F_SBIA = F_LB + 512;         // ends float 2704
constexpr int SM_A   = 12288;              // 4 x 9216 = 36864
constexpr int SM_B   = SM_A + 4 * A_STAGE_BYTES;        // 49152
constexpr int SMEM_BYTES = SM_B + 2 * B_STAGE_BYTES;    // 196608
constexpr int F_STAGE = SM_B >> 2;         // epilogue staging [512 n][72]f reuses B region

__global__ __launch_bounds__(512, 1)
void fused_kernel(const float* __restrict__ x,
                  const float* __restrict__ prelu_a,
                  const float* __restrict__ lnw,
                  const float* __restrict__ lnb,
                  float* __restrict__ out) {
    extern __shared__ float smf[];
    const uint32_t smb = smem_u32(smf);
    const int tid = threadIdx.x;
    const int b = blockIdx.x >> 8;
    const int t = blockIdx.x & 255;

    // epilogue constants
    smf[F_LW + tid]   = lnw[tid];
    smf[F_LB + tid]   = lnb[tid];
    smf[F_SBIA + tid] = g_sbias[b * 512 + tid];

    if (tid == 0) {
        mbar_init(smb + MB_TMA + 0, 1);
        mbar_init(smb + MB_TMA + 8, 1);
#pragma unroll
        for (int i = 0; i < 4; ++i) mbar_init(smb + MB_ARDY + 8 * i, 512);
        mbar_init(smb + MB_RD + 0, 16);
        mbar_init(smb + MB_RD + 8, 16);
    }
    __syncthreads();

    const int lane = tid & 31, w = tid >> 5;
    const int wm = w >> 3, wn = w & 7;
    const int qid = lane >> 2, tig = lane & 3;
    const int akt = tid >> 4;            // 0..31  (k-pair row)
    const int am0 = (tid & 15) * 4;      // m quad

    const uint32_t b_lane_off =
        (uint32_t)((((lane >> 4) * 8 + (lane & 7)) * SBW + ((lane >> 3) & 1) * 4) * 4);

    const float* xa_base = x + (size_t)b * 512 * 16384 + t * 64 + am0;
    auto ldgA = [&](int s, float4& f0, float4& f1) {
        const float* p = xa_base + (size_t)(s * KSTAGE + 2 * akt) * 16384;
        f0 = *(const float4*)p;
        f1 = *(const float4*)(p + 16384);
    };
    auto stsA = [&](int abuf, const float4& f0, const float4& f1) {
        uint32_t w0 = packh2(f0.x, f1.x);
        uint32_t w1 = packh2(f0.y, f1.y);
        uint32_t w2 = packh2(f0.z, f1.z);
        uint32_t w3 = packh2(f0.w, f1.w);
        uint32_t dst = smb + SM_A + abuf * A_STAGE_BYTES + (akt * SAW + am0) * 4;
        asm volatile("st.shared.v4.b32 [%0], {%1,%2,%3,%4};"
                     :: "r"(dst), "r"(w0), "r"(w1), "r"(w2), "r"(w3));
    };

    float acc[2][8][4];
#pragma unroll
    for (int mt = 0; mt < 2; ++mt)
#pragma unroll
        for (int nt = 0; nt < 8; ++nt)
#pragma unroll
            for (int r = 0; r < 4; ++r) acc[mt][nt][r] = 0.f;

    // prologue: A stages 0,1 + B stages 0,1
    {
        float4 f0, f1;
        ldgA(0, f0, f1); stsA(0, f0, f1);
        mbar_arrive(smb + MB_ARDY + 0);
        ldgA(1, f0, f1); stsA(1, f0, f1);
        mbar_arrive(smb + MB_ARDY + 8);
    }
    if (tid == 0) {
        mbar_expect_tx(smb + MB_TMA + 0, B_STAGE_BYTES);
        bulk_g2s(smb + SM_B, g_wst, B_STAGE_BYTES, smb + MB_TMA + 0);
        mbar_expect_tx(smb + MB_TMA + 8, B_STAGE_BYTES);
        bulk_g2s(smb + SM_B + B_STAGE_BYTES, g_wst + 512 * SBW, B_STAGE_BYTES,
                 smb + MB_TMA + 8);
    }

    float4 pf0, pf1;   // A prefetch registers
    for (int s = 0; s < NSTAGES; ++s) {
        const int buf = s & 1;
        const uint32_t par2 = (uint32_t)((s >> 1) & 1);   // tma / rd parity
        if (s + 2 < NSTAGES) ldgA(s + 2, pf0, pf1);

        mbar_wait(smb + MB_TMA + 8 * buf, par2);                       // B(s) full
        mbar_wait(smb + MB_ARDY + 8 * (s & 3), (uint32_t)((s >> 2) & 1)); // A(s) ready

        const uint32_t* A2 = (const uint32_t*)((const char*)smf + SM_A +
                                               (s & 3) * A_STAGE_BYTES);
        const uint32_t bwarp = smb + SM_B + buf * B_STAGE_BYTES +
                               (uint32_t)(wn * 64 * SBW * 4) + b_lane_off;

#pragma unroll
        for (int c4 = 0; c4 < 4; ++c4) {
            const int kt0 = c4 * 8;
            uint32_t bb[4][4];
#pragma unroll
            for (int np = 0; np < 4; ++np)
                ldsm_x4(bb[np][0], bb[np][1], bb[np][2], bb[np][3],
                        bwarp + (uint32_t)(np * 16 * SBW * 4 + kt0 * 4));
            uint32_t a[2][4];
#pragma unroll
            for (int mt = 0; mt < 2; ++mt) {
                const int m0 = wm * 32 + mt * 16 + qid;
                a[mt][0] = A2[(kt0 + tig) * SAW + m0];
                a[mt][1] = A2[(kt0 + tig) * SAW + m0 + 8];
                a[mt][2] = A2[(kt0 + 4 + tig) * SAW + m0];
                a[mt][3] = A2[(kt0 + 4 + tig) * SAW + m0 + 8];
            }
#pragma unroll
            for (int np = 0; np < 4; ++np) {
                mma_f16(acc[0][np * 2],     a[0], bb[np][0], bb[np][1]);
                mma_f16(acc[1][np * 2],     a[1], bb[np][0], bb[np][1]);
                mma_f16(acc[0][np * 2 + 1], a[0], bb[np][2], bb[np][3]);
                mma_f16(acc[1][np * 2 + 1], a[1], bb[np][2], bb[np][3]);
            }
        }

        // reads of A(s)/B(s) complete for this warp
        if (lane == 0) mbar_arrive(smb + MB_RD + 8 * buf);

        if (s + 2 < NSTAGES) {
            stsA((s + 2) & 3, pf0, pf1);
            mbar_arrive(smb + MB_ARDY + 8 * ((s + 2) & 3));
            if (w == s && lane == 0) {   // rotating issuer warp (s = 0..5)
                mbar_wait(smb + MB_RD + 8 * buf, par2);  // all warps read B(s)
                mbar_expect_tx(smb + MB_TMA + 8 * buf, B_STAGE_BYTES);
                bulk_g2s(smb + SM_B + buf * B_STAGE_BYTES,
                         g_wst + (s + 2) * 512 * SBW, B_STAGE_BYTES,
                         smb + MB_TMA + 8 * buf);
            }
        }
    }

    __syncthreads();   // everyone done with mainloop; B region becomes staging

    // ---------------- epilogue ----------------
    const float pa = prelu_a[0];

    float srow[4] = {0.f, 0.f, 0.f, 0.f};
    float qrow[4] = {0.f, 0.f, 0.f, 0.f};
#pragma unroll
    for (int mt = 0; mt < 2; ++mt)
#pragma unroll
        for (int nt = 0; nt < 8; ++nt)
#pragma unroll
            for (int r = 0; r < 4; ++r) {
                const int half = r >> 1;
                const int n = wn * 64 + nt * 8 + tig * 2 + (r & 1);
                const int rrow = wm * 32 + mt * 16 + half * 8 + qid;
                float v = acc[mt][nt][r] + smf[F_SBIA + n];
                v = (v >= 0.f) ? v : pa * v;
                smf[F_STAGE + n * 72 + rrow] = v;
                srow[mt * 2 + half] += v;
                qrow[mt * 2 + half] += v * v;
            }
#pragma unroll
    for (int off = 1; off <= 2; off <<= 1)
#pragma unroll
        for (int i = 0; i < 4; ++i) {
            srow[i] += __shfl_xor_sync(0xffffffffu, srow[i], off);
            qrow[i] += __shfl_xor_sync(0xffffffffu, qrow[i], off);
        }
    if (tig == 0) {
#pragma unroll
        for (int i = 0; i < 4; ++i) {
            const int rrow = wm * 32 + (i >> 1) * 16 + (i & 1) * 8 + qid;
            smf[F_RS + rrow * 8 + wn] = srow[i];
            smf[F_RQ + rrow * 8 + wn] = qrow[i];
        }
    }
    __syncthreads();
    if (tid < 64) {
        float s8 = 0.f, q8 = 0.f;
#pragma unroll
        for (int j = 0; j < 8; ++j) {
            s8 += smf[F_RS + tid * 8 + j];
            q8 += smf[F_RQ + tid * 8 + j];
        }
        const float mu = s8 * (1.f / 512.f);
        float var = q8 * (1.f / 512.f) - mu * mu;
        var = fmaxf(var, 0.f);
        smf[F_MU + tid] = mu;
        smf[F_RSTD + tid] = rsqrtf(var + 1e-8f);
    }
    __syncthreads();

    const float mu0 = smf[F_MU + lane],      rs0 = smf[F_RSTD + lane];
    const float mu1 = smf[F_MU + lane + 32], rs1 = smf[F_RSTD + lane + 32];
    const size_t base = ((size_t)b * 512 * 256 + t) * 64;
#pragma unroll 4
    for (int i = 0; i < 32; ++i) {
        const int n = i * 16 + w;
        const float lw = smf[F_LW + n], lb = smf[F_LB + n];
        const float v0 = smf[F_STAGE + n * 72 + lane];
        const float v1 = smf[F_STAGE + n * 72 + lane + 32];
        const size_t gi = base + (size_t)n * 16384 + lane;
        out[gi]      = (v0 - mu0) * rs0 * lw + lb + x[gi];
        out[gi + 32] = (v1 - mu1) * rs1 * lw + lb + x[gi + 32];
    }
}

// ---------------- launch ----------------

extern "C" void kernel_launch(void* const* d_in, const int* in_sizes, int n_in,
                              void* d_out, int out_size) {
    (void)in_sizes; (void)n_in; (void)out_size;
    const float* x      = (const float*)d_in[0];
    const float* s      = (const float*)d_in[1];
    // d_in[2..4]: prelu1_a, ln1_w, ln1_b — dead code in the reference
    const float* W      = (const float*)d_in[5];
    const float* bias   = (const float*)d_in[6];
    const float* prelu2 = (const float*)d_in[7];
    const float* ln2w   = (const float*)d_in[8];
    const float* ln2b   = (const float*)d_in[9];
    float* out = (float*)d_out;

    cudaFuncSetAttribute(fused_kernel,
                         cudaFuncAttributeMaxDynamicSharedMemorySize, SMEM_BYTES);

    prep_kernel<<<832, 256>>>(s, W, bias);
    fused_kernel<<<1024, 512, SMEM_BYTES>>>(x, prelu2, ln2w, ln2b, out);
}